// round 15
// baseline (speedup 1.0000x reference)
#include <cuda_runtime.h>
#include <cuda_fp16.h>
#include <math.h>
#include <cstdint>

// Problem constants
#define S_   32
#define FRM  8
#define CLS_ 32
#define D_   512
#define HWA2 64      // 8*8
#define HWV2 196     // 14*14
#define HWP  208     // padded to 13*16
#define DOUT 128
#define BA   (S_*CLS_)   // 1024
#define BV   (S_*FRM)    // 256

// ---------------- device scratch ----------------
__device__ float d_ta[BA * DOUT];
__device__ float d_camsum[BV * CLS_];
__device__ float d_tv[BV * CLS_ * DOUT];
__device__ float d_wbs[DOUT];
// fp16 permuted buffers
__device__ __half d_wt_h[D_ * D_];                      // [o][kperm]
__device__ __half d_fv_h[(size_t)BV * D_ * HWP];        // [b][i][hwperm]
__device__ __half d_cam_h[(size_t)BV * CLS_ * HWP];     // [b][c][hwperm]
__device__ __half d_g_h[(size_t)BV * CLS_ * D_];        // [m][kperm]
__device__ __half d_wvs_h[DOUT * D_];                   // [o][kperm]

// =============== small asm helpers ===============
__device__ __forceinline__ uint32_t smem_to_u32(const void* p) {
    uint32_t a;
    asm("{ .reg .u64 t; cvta.to.shared.u64 t, %1; cvt.u32.u64 %0, t; }" : "=r"(a) : "l"(p));
    return a;
}
#define CP_ASYNC16(sm, g) \
    asm volatile("cp.async.cg.shared.global [%0], [%1], 16;" :: "r"((uint32_t)(sm)), "l"(g) : "memory")
#define CP_ASYNC_COMMIT() asm volatile("cp.async.commit_group;" ::: "memory")
#define CP_ASYNC_WAIT0()  asm volatile("cp.async.wait_group 0;" ::: "memory")
#define CP_ASYNC_WAIT1()  asm volatile("cp.async.wait_group 1;" ::: "memory")

#define LDS64(r0, r1, addr) \
    asm volatile("ld.shared.v2.b32 {%0,%1}, [%2];" : "=r"(r0), "=r"(r1) : "r"((uint32_t)(addr)))

#define MMA_F16(d, a, b) \
    asm volatile("mma.sync.aligned.m16n8k16.row.col.f32.f16.f16.f32 " \
        "{%0,%1,%2,%3}, {%4,%5,%6,%7}, {%8,%9}, {%0,%1,%2,%3};" \
        : "+f"((d)[0]), "+f"((d)[1]), "+f"((d)[2]), "+f"((d)[3]) \
        : "r"((a)[0]), "r"((a)[1]), "r"((a)[2]), "r"((a)[3]), "r"((b)[0]), "r"((b)[1]))

__device__ __forceinline__ uint32_t pack_h2(__half a, __half b) {
    __half2 p = __halves2half2(a, b);
    return *(uint32_t*)&p;
}

// k-permutation within a 16-group (m16n8k16 frag layout):
// word w (fp16 pair): w even -> k = w ; w odd -> k = w + 7.
// inverse (even k e): w = (e < 8) ? e : e - 7.

// =====================================================================
// Prep 1: Wt fp32 -> permuted fp16
// =====================================================================
__global__ __launch_bounds__(256) void k_cvt_w(const float* __restrict__ Wt) {
    int idx = blockIdx.x * 256 + threadIdx.x;
    int o = idx >> 5, g = idx & 31;
    const float* src = Wt + (size_t)o * D_ + g * 16;
    float v[16];
#pragma unroll
    for (int q = 0; q < 4; q++) {
        float4 f = *(const float4*)(src + q * 4);
        v[q * 4 + 0] = f.x; v[q * 4 + 1] = f.y; v[q * 4 + 2] = f.z; v[q * 4 + 3] = f.w;
    }
    uint32_t hw_[8];
#pragma unroll
    for (int w = 0; w < 8; w++) {
        int k = (w & 1) ? (w + 7) : w;
        hw_[w] = pack_h2(__float2half_rn(v[k]), __float2half_rn(v[k + 1]));
    }
    uint32_t* dh = (uint32_t*)d_wt_h + (size_t)o * 256 + g * 8;
    *(uint4*)(dh + 0) = make_uint4(hw_[0], hw_[1], hw_[2], hw_[3]);
    *(uint4*)(dh + 4) = make_uint4(hw_[4], hw_[5], hw_[6], hw_[7]);
}

// =====================================================================
// Prep (video): feat_v rows then cam rows -> fp16 hw-permuted (pad 208)
// =====================================================================
__global__ __launch_bounds__(256) void k_prep_fvcam(const float* __restrict__ feat_v,
                                                    const float* __restrict__ cam) {
    const int t = threadIdx.x;
    const int g = t & 15, rloc = t >> 4;
    const long row = (long)blockIdx.x * 16 + rloc;
    const bool is_cam = (row >= (long)BV * D_);
    long r2 = 0;
    const float* src;
    uint32_t* dst;
    if (!is_cam) {
        src = feat_v + row * HWV2;
        dst = (uint32_t*)d_fv_h + row * (HWP / 2) + g * 8;
    } else {
        r2 = row - (long)BV * D_;
        src = cam + r2 * HWV2;
        dst = (uint32_t*)d_cam_h + r2 * (HWP / 2) + g * 8;
    }
    const bool active = (g < 13);
    float v[16];
#pragma unroll
    for (int qq = 0; qq < 4; qq++) {
        int idx4 = g * 4 + qq;
        if (active && idx4 < 49) {
            float4 f = *(const float4*)(src + idx4 * 4);
            v[qq * 4 + 0] = f.x; v[qq * 4 + 1] = f.y;
            v[qq * 4 + 2] = f.z; v[qq * 4 + 3] = f.w;
        } else {
            v[qq * 4 + 0] = 0.f; v[qq * 4 + 1] = 0.f;
            v[qq * 4 + 2] = 0.f; v[qq * 4 + 3] = 0.f;
        }
    }
    if (active) {
        uint32_t wv[8];
#pragma unroll
        for (int w = 0; w < 8; w++) {
            int k = (w & 1) ? (w + 7) : w;
            wv[w] = pack_h2(__float2half_rn(v[k]), __float2half_rn(v[k + 1]));
        }
        *(uint4*)(dst + 0) = make_uint4(wv[0], wv[1], wv[2], wv[3]);
        *(uint4*)(dst + 4) = make_uint4(wv[4], wv[5], wv[6], wv[7]);
    }
    if (is_cam) {
        float s = 0.f;
#pragma unroll
        for (int q = 0; q < 16; q++) s += v[q];
        s += __shfl_xor_sync(0xffffffffu, s, 1);
        s += __shfl_xor_sync(0xffffffffu, s, 2);
        s += __shfl_xor_sync(0xffffffffu, s, 4);
        s += __shfl_xor_sync(0xffffffffu, s, 8);
        if (g == 0) d_camsum[r2] = s;
    }
}

// =====================================================================
// k_fa_mma: fa[b,o] = max_hw( feat[b,:,hw] . Wt[o,:] ) + bt[o]
// 128 threads (4 warps), 2 CTAs/SM. Warp tile 64o x 32hw.
// FUSED ta epilogue: ta[b,o] = fa[b,:].Wa[o,:] + ba[o]  (fp32, L2-resident Wa)
// =====================================================================
#define FEAT_OFF  1024
#define FEAT_ROWB 1056
#define FEAT_SZ   (64 * FEAT_ROWB)
#define WT_OFF    (FEAT_OFF + FEAT_SZ)
#define WT_ROWB   160
#define WT_BUFSZ  (128 * WT_ROWB)
#define FA_SMEM   (WT_OFF + 2 * WT_BUFSZ)   // 109568

__device__ __forceinline__ void fa_load_wt(uint32_t sb, int buf, int otp, int kc, int t) {
#pragma unroll
    for (int r = 0; r < 8; r++) {
        int idx = r * 128 + t;          // 1024 x 16B
        int row = idx >> 3, c = idx & 7;
        const __half* src = d_wt_h + ((size_t)(otp * 128 + row) * D_ + kc * 64 + c * 8);
        uint32_t dst = sb + WT_OFF + buf * WT_BUFSZ + row * WT_ROWB + c * 16;
        CP_ASYNC16(dst, src);
    }
}

__global__ void __launch_bounds__(128, 2) k_fa_mma(const float* __restrict__ feat_a,
                                                   const float* __restrict__ bt,
                                                   const float* __restrict__ Wa,
                                                   const float* __restrict__ ba) {
    extern __shared__ char smem[];
    float* red = (float*)smem;          // 256 floats
    uint32_t sb = smem_to_u32(smem);
    const int b = blockIdx.x;
    const int t = threadIdx.x;
    const int w = t >> 5, lane = t & 31;
    const int oy = w >> 1, hx = w & 1;  // 2 o-groups(64) x 2 hw-groups(32)
    const int j = lane & 3, r4 = lane >> 2;

    // ---- pipelined prologue: feat_a fp32 -> feat smem fp16 ----
    {
        const float* fsrc = feat_a + (size_t)b * (D_ * HWA2);
        const int hw = t & 63, kseg = t >> 6;   // kseg in {0,1}
#pragma unroll
        for (int r = 0; r < 8; r++) {
            int idx = r * 128 + t;              // 1024 x 16B
            int row = idx >> 4, c4 = idx & 15;
            CP_ASYNC16(sb + WT_OFF + row * 272 + c4 * 16,
                       fsrc + (size_t)row * HWA2 + c4 * 4);
        }
        CP_ASYNC_COMMIT();
        for (int c = 0; c < 8; c++) {
            if (c + 1 < 8) {
                uint32_t bb = sb + WT_OFF + ((c + 1) & 1) * WT_BUFSZ;
#pragma unroll
                for (int r = 0; r < 8; r++) {
                    int idx = r * 128 + t;
                    int row = idx >> 4, c4 = idx & 15;
                    CP_ASYNC16(bb + row * 272 + c4 * 16,
                               fsrc + (size_t)((c + 1) * 64 + row) * HWA2 + c4 * 4);
                }
                CP_ASYNC_COMMIT();
                CP_ASYNC_WAIT1();
            } else {
                CP_ASYNC_WAIT0();
            }
            __syncthreads();
            const float* stg = (const float*)(smem + WT_OFF + (c & 1) * WT_BUFSZ);
#pragma unroll
            for (int g2 = 0; g2 < 2; g2++) {
                const int kbase = kseg * 32 + g2 * 16;
                uint32_t pk[8];
#pragma unroll
                for (int ww = 0; ww < 8; ww++) {
                    int k = (ww & 1) ? (ww + 7) : ww;
                    pk[ww] = pack_h2(__float2half_rn(stg[(kbase + k) * 68 + hw]),
                                     __float2half_rn(stg[(kbase + k + 1) * 68 + hw]));
                }
                char* dst = smem + FEAT_OFF + hw * FEAT_ROWB
                          + (c * 128 + kseg * 64 + g2 * 32);
                *(uint4*)dst = make_uint4(pk[0], pk[1], pk[2], pk[3]);
                *(uint4*)(dst + 16) = make_uint4(pk[4], pk[5], pk[6], pk[7]);
            }
            __syncthreads();
        }
    }

    fa_load_wt(sb, 0, 0, 0, t);
    CP_ASYNC_COMMIT();

    float acc[4][4][4];
#pragma unroll
    for (int mf = 0; mf < 4; mf++)
#pragma unroll
        for (int nf = 0; nf < 4; nf++)
#pragma unroll
            for (int q = 0; q < 4; q++) acc[mf][nf][q] = 0.f;

    float fa_reg[4];                    // fa value for o = otp*128 + t

    const int oA = oy * 64 + r4;
    const int hwB = hx * 32 + r4;

    for (int it = 0; it < 32; it++) {
        const int otp = it >> 3, kc = it & 7, buf = it & 1;
        if (it + 1 < 32) {
            fa_load_wt(sb, buf ^ 1, (it + 1) >> 3, (it + 1) & 7, t);
            CP_ASYNC_COMMIT();
            CP_ASYNC_WAIT1();
        } else {
            CP_ASYNC_WAIT0();
        }
        __syncthreads();

        const uint32_t wtb = sb + WT_OFF + buf * WT_BUFSZ;
#pragma unroll
        for (int kst = 0; kst < 4; kst++) {
            const int ks = kc * 4 + kst;
            uint32_t a[4][4];
#pragma unroll
            for (int mf = 0; mf < 4; mf++) {
                uint32_t base = wtb + (oA + mf * 16) * WT_ROWB + kst * 32 + j * 8;
                LDS64(a[mf][0], a[mf][2], base);
                LDS64(a[mf][1], a[mf][3], base + 8 * WT_ROWB);
            }
            uint32_t bh[4][2];
#pragma unroll
            for (int nf = 0; nf < 4; nf++) {
                uint32_t bb = sb + FEAT_OFF + (hwB + nf * 8) * FEAT_ROWB + ks * 32 + j * 8;
                LDS64(bh[nf][0], bh[nf][1], bb);
            }
#pragma unroll
            for (int mf = 0; mf < 4; mf++)
#pragma unroll
                for (int nf = 0; nf < 4; nf++)
                    MMA_F16(acc[mf][nf], a[mf], bh[nf]);
        }

        if (kc == 7) {
#pragma unroll
            for (int mf = 0; mf < 4; mf++) {
                float m0 = -3.4e38f, m1 = -3.4e38f;
#pragma unroll
                for (int nf = 0; nf < 4; nf++) {
                    m0 = fmaxf(m0, fmaxf(acc[mf][nf][0], acc[mf][nf][1]));
                    m1 = fmaxf(m1, fmaxf(acc[mf][nf][2], acc[mf][nf][3]));
                }
                m0 = fmaxf(m0, __shfl_xor_sync(0xffffffffu, m0, 1));
                m0 = fmaxf(m0, __shfl_xor_sync(0xffffffffu, m0, 2));
                m1 = fmaxf(m1, __shfl_xor_sync(0xffffffffu, m1, 1));
                m1 = fmaxf(m1, __shfl_xor_sync(0xffffffffu, m1, 2));
                if (j == 0) {
                    int o0 = oy * 64 + mf * 16 + r4;
                    red[o0 * 2 + hx] = m0;
                    red[(o0 + 8) * 2 + hx] = m1;
                }
            }
            __syncthreads();
            {
                int o = t;   // 128 threads, 128 o-rows of this chunk
                float v = fmaxf(red[o * 2], red[o * 2 + 1]);
                fa_reg[otp] = v + bt[otp * 128 + o];
            }
#pragma unroll
            for (int mf = 0; mf < 4; mf++)
#pragma unroll
                for (int nf = 0; nf < 4; nf++)
#pragma unroll
                    for (int q = 0; q < 4; q++) acc[mf][nf][q] = 0.f;
        }
        __syncthreads();
    }

    // ---- fused ta epilogue: ta[b][t] = sum_k fa[k] * Wa[t][k] + ba[t] ----
    float* fa_s = (float*)(smem + FEAT_OFF);   // feat region is dead now
#pragma unroll
    for (int p = 0; p < 4; p++) fa_s[p * 128 + t] = fa_reg[p];
    __syncthreads();
    {
        float acc_ta = ba[t];
        const float4* war = (const float4*)(Wa + (size_t)t * D_);
#pragma unroll 8
        for (int k4 = 0; k4 < 128; k4++) {
            float4 wv4 = war[k4];
            const float* fs = fa_s + k4 * 4;
            acc_ta = fmaf(wv4.x, fs[0], acc_ta);
            acc_ta = fmaf(wv4.y, fs[1], acc_ta);
            acc_ta = fmaf(wv4.z, fs[2], acc_ta);
            acc_ta = fmaf(wv4.w, fs[3], acc_ta);
        }
        d_ta[(size_t)b * DOUT + t] = acc_ta;
    }
}

// =====================================================================
// k_g_mma: g[b,c,i] = sum_hw cam*feat_v -> fp16 k-permuted d_g_h
// =====================================================================
#define GC_OFF   1024
#define G_ROWB   416
#define GC_SZ    (32 * G_ROWB)
#define GF_OFF   (GC_OFF + GC_SZ)
#define GF_BUFSZ (128 * G_ROWB)
#define KG_SMEM  (GF_OFF + 2 * GF_BUFSZ)

__device__ __forceinline__ void g_load_fv(uint32_t sb, int buf, int b, int ic, int t) {
#pragma unroll
    for (int r = 0; r < 13; r++) {
        int idx = r * 256 + t;
        int row = idx / 26, c = idx % 26;
        const __half* src = d_fv_h + ((size_t)(b * D_) + ic * 128 + row) * HWP + c * 8;
        uint32_t dst = sb + GF_OFF + buf * GF_BUFSZ + row * G_ROWB + c * 16;
        CP_ASYNC16(dst, src);
    }
}

__global__ void __launch_bounds__(256, 1) k_g_mma() {
    extern __shared__ char smem[];
    uint32_t sb = smem_to_u32(smem);
    const int b = blockIdx.x;
    const int t = threadIdx.x;
    const int w = t >> 5, lane = t & 31;
    const int my = w & 1, ix = w >> 1;
    const int j = lane & 3, r4 = lane >> 2;

#pragma unroll
    for (int r = 0; r < 4; r++) {
        int idx = r * 256 + t;
        if (idx < 832) {
            int row = idx / 26, c = idx % 26;
            const __half* src = d_cam_h + ((size_t)(b * CLS_) + row) * HWP + c * 8;
            CP_ASYNC16(sb + GC_OFF + row * G_ROWB + c * 16, src);
        }
    }
    g_load_fv(sb, 0, b, 0, t);
    CP_ASYNC_COMMIT();

    for (int ic = 0; ic < 4; ic++) {
        const int buf = ic & 1;
        if (ic + 1 < 4) {
            g_load_fv(sb, buf ^ 1, b, ic + 1, t);
            CP_ASYNC_COMMIT();
            CP_ASYNC_WAIT1();
        } else {
            CP_ASYNC_WAIT0();
        }
        __syncthreads();

        float acc[4][4];
#pragma unroll
        for (int nf = 0; nf < 4; nf++)
#pragma unroll
            for (int q = 0; q < 4; q++) acc[nf][q] = 0.f;

        const uint32_t fvb = sb + GF_OFF + buf * GF_BUFSZ;
#pragma unroll
        for (int kst = 0; kst < 13; kst++) {
            uint32_t a[4];
            uint32_t abase = sb + GC_OFF + (my * 16 + r4) * G_ROWB + kst * 32 + j * 8;
            LDS64(a[0], a[2], abase);
            LDS64(a[1], a[3], abase + 8 * G_ROWB);
            uint32_t bh[4][2];
#pragma unroll
            for (int nf = 0; nf < 4; nf++) {
                uint32_t bb = fvb + (ix * 32 + nf * 8 + r4) * G_ROWB + kst * 32 + j * 8;
                LDS64(bh[nf][0], bh[nf][1], bb);
            }
#pragma unroll
            for (int nf = 0; nf < 4; nf++)
                MMA_F16(acc[nf], a, bh[nf]);
        }

        const int c0 = my * 16 + r4;
#pragma unroll
        for (int nf = 0; nf < 4; nf++) {
            int ig = ic * 128 + ix * 32 + nf * 8 + 2 * j;
            int gg = ig >> 4, rm = ig & 15;
            int wd = (rm < 8) ? rm : (rm - 7);
            int word = gg * 8 + wd;
            uint32_t* g0 = (uint32_t*)d_g_h + ((size_t)b * CLS_ + c0) * 256 + word;
            *g0 = pack_h2(__float2half_rn(acc[nf][0]), __float2half_rn(acc[nf][1]));
            uint32_t* g1 = (uint32_t*)d_g_h + ((size_t)b * CLS_ + c0 + 8) * 256 + word;
            *g1 = pack_h2(__float2half_rn(acc[nf][2]), __float2half_rn(acc[nf][3]));
        }
        __syncthreads();
    }
}

// =====================================================================
// wbs[o] = Wv[o,:].bs
// =====================================================================
__global__ void k_wbs(const float* __restrict__ Wv, const float* __restrict__ bs) {
    int o = blockIdx.x, lane = threadIdx.x;
    float s = 0.f;
    for (int d = lane; d < D_; d += 32) s = fmaf(Wv[(size_t)o * D_ + d], bs[d], s);
#pragma unroll
    for (int off = 16; off; off >>= 1) s += __shfl_xor_sync(0xffffffffu, s, off);
    if (!lane) d_wbs[o] = s;
}

// =====================================================================
// Wvs[o,i] = sum_d Wv[o,d]*Ws[d,i]  (fp16 permuted out)
// =====================================================================
__global__ __launch_bounds__(256) void k_wvs(const float* __restrict__ Wv,
                                             const float* __restrict__ Ws) {
    __shared__ float sV[32][65];
    __shared__ float sS[64][65];
    const int oT = blockIdx.x, iT = blockIdx.y;
    const int t = threadIdx.x;
    const int tx = t & 31, ty = t >> 5;

    float acc[4][2];
#pragma unroll
    for (int a = 0; a < 4; a++) { acc[a][0] = 0.f; acc[a][1] = 0.f; }

    for (int k0 = 0; k0 < D_; k0 += 64) {
#pragma unroll
        for (int r = 0; r < 8; r++) {
            int idx = r * 256 + t;
            int o = idx >> 6, kk = idx & 63;
            sV[o][kk] = Wv[(size_t)(oT * 32 + o) * D_ + k0 + kk];
        }
#pragma unroll
        for (int r = 0; r < 16; r++) {
            int idx = r * 256 + t;
            int kk = idx >> 6, i = idx & 63;
            sS[kk][i] = Ws[(size_t)(k0 + kk) * D_ + iT * 64 + i];
        }
        __syncthreads();
#pragma unroll
        for (int kk = 0; kk < 64; kk++) {
            float bb0 = sS[kk][tx], bb1 = sS[kk][tx + 32];
#pragma unroll
            for (int a = 0; a < 4; a++) {
                float av = sV[ty * 4 + a][kk];
                acc[a][0] = fmaf(av, bb0, acc[a][0]);
                acc[a][1] = fmaf(av, bb1, acc[a][1]);
            }
        }
        __syncthreads();
    }
#pragma unroll
    for (int a = 0; a < 4; a++) {
        int o = oT * 32 + ty * 4 + a;
#pragma unroll
        for (int half_ = 0; half_ < 2; half_++) {
            int i = iT * 64 + tx + 32 * half_;
            float v = acc[a][half_];
            int gg = i >> 4;
            int ke = (i & ~1) & 15;
            int wd = (ke < 8) ? ke : (ke - 7);
            d_wvs_h[(size_t)o * D_ + gg * 16 + wd * 2 + (i & 1)] = __float2half_rn(v);
        }
    }
}

// =====================================================================
// k_tv_mma: 128m x 128o tiles (grid 64)
// =====================================================================
#define TV_B_OFF   0
#define TV_B_ROWB  1056
#define TV_A_OFF   (128 * TV_B_ROWB)
#define TV_A_ROWB  288
#define TV_A_BUFSZ (128 * TV_A_ROWB)
#define TV_SMEM    (TV_A_OFF + 2 * TV_A_BUFSZ)

__device__ __forceinline__ void tv_load_a(uint32_t sb, int buf, const __half* A,
                                          int m0, int kc, int t) {
#pragma unroll
    for (int r = 0; r < 8; r++) {
        int idx = r * 256 + t;
        int row = idx >> 4, c = idx & 15;
        const __half* src = A + ((size_t)(m0 + row) * D_ + kc * 128 + c * 8);
        uint32_t dst = sb + TV_A_OFF + buf * TV_A_BUFSZ + row * TV_A_ROWB + c * 16;
        CP_ASYNC16(dst, src);
    }
}

__global__ void __launch_bounds__(256, 1) k_tv_mma(const float* __restrict__ bv) {
    extern __shared__ char smem[];
    uint32_t sb = smem_to_u32(smem);
    const int m0 = blockIdx.x * 128;
    const int t = threadIdx.x;
    const int w = t >> 5, lane = t & 31;
    const int mgrp = w & 3, ogrp = w >> 2;
    const int j = lane & 3, r4 = lane >> 2;

    float acc[2][8][4];
#pragma unroll
    for (int mf = 0; mf < 2; mf++)
#pragma unroll
        for (int nf = 0; nf < 8; nf++)
#pragma unroll
            for (int q = 0; q < 4; q++) acc[mf][nf][q] = 0.f;

#pragma unroll
    for (int r = 0; r < 32; r++) {
        int idx = r * 256 + t;
        int row = idx >> 6, c = idx & 63;
        CP_ASYNC16(sb + TV_B_OFF + row * TV_B_ROWB + c * 16,
                   d_wvs_h + ((size_t)row * D_ + c * 8));
    }
    tv_load_a(sb, 0, d_g_h, m0, 0, t);
    CP_ASYNC_COMMIT();

    for (int kc = 0; kc < 4; kc++) {
        const int buf = kc & 1;
        if (kc + 1 < 4) {
            tv_load_a(sb, buf ^ 1, d_g_h, m0, kc + 1, t);
            CP_ASYNC_COMMIT();
            CP_ASYNC_WAIT1();
        } else {
            CP_ASYNC_WAIT0();
        }
        __syncthreads();

#pragma unroll
        for (int kst = 0; kst < 8; kst++) {
            const int ks = kc * 8 + kst;
            uint32_t a[2][4];
#pragma unroll
            for (int mf = 0; mf < 2; mf++) {
                uint32_t base = sb + TV_A_OFF + buf * TV_A_BUFSZ
                              + (mgrp * 32 + mf * 16 + r4) * TV_A_ROWB + kst * 32 + j * 8;
                LDS64(a[mf][0], a[mf][2], base);
                LDS64(a[mf][1], a[mf][3], base + 8 * TV_A_ROWB);
            }
            uint32_t bh[8][2];
#pragma unroll
            for (int nf = 0; nf < 8; nf++) {
                uint32_t bb = sb + TV_B_OFF + (ogrp * 64 + nf * 8 + r4) * TV_B_ROWB
                            + ks * 32 + j * 8;
                LDS64(bh[nf][0], bh[nf][1], bb);
            }
#pragma unroll
            for (int mf = 0; mf < 2; mf++)
#pragma unroll
                for (int nf = 0; nf < 8; nf++)
                    MMA_F16(acc[mf][nf], a[mf], bh[nf]);
        }
        __syncthreads();
    }

#pragma unroll
    for (int mf = 0; mf < 2; mf++) {
        int mr0 = m0 + mgrp * 32 + mf * 16 + r4;
        int mr1 = mr0 + 8;
        float cs0 = d_camsum[mr0], cs1 = d_camsum[mr1];
        float inv0 = 1.f / (cs0 + 1e-10f), inv1 = 1.f / (cs1 + 1e-10f);
#pragma unroll
        for (int nf = 0; nf < 8; nf++) {
            int o0 = ogrp * 64 + nf * 8 + 2 * j;
            float wb0 = d_wbs[o0], wb1 = d_wbs[o0 + 1];
            float bv0 = bv[o0], bv1 = bv[o0 + 1];
            d_tv[(size_t)mr0 * DOUT + o0]     = (acc[mf][nf][0] + wb0 * cs0) * inv0 + bv0;
            d_tv[(size_t)mr0 * DOUT + o0 + 1] = (acc[mf][nf][1] + wb1 * cs0) * inv0 + bv1;
            d_tv[(size_t)mr1 * DOUT + o0]     = (acc[mf][nf][2] + wb0 * cs1) * inv1 + bv0;
            d_tv[(size_t)mr1 * DOUT + o0 + 1] = (acc[mf][nf][3] + wb1 * cs1) * inv1 + bv1;
        }
    }
}

// =====================================================================
// losses
// =====================================================================
__global__ void k_loss(const float* __restrict__ pred_a, const float* __restrict__ pred_v,
                       const int* __restrict__ rand_frames, const int* __restrict__ rand_classes,
                       float* __restrict__ out) {
    const int s = blockIdx.x, c = blockIdx.y;
    const int f = threadIdx.x >> 5, lane = threadIdx.x & 31;

    const float pa = pred_a[s * CLS_ + c];
    const bool aa = pa > 0.3f;
    const int num = (int)(pa * (float)FRM);

    const float* tap = d_ta + (size_t)(s * CLS_ + c) * DOUT;
    const float* tvp = d_tv + (size_t)((s * FRM + f) * CLS_ + c) * DOUT;
    const int rf = rand_frames[(s * CLS_ + c) * FRM + f];
    const int rc = rand_classes[(s * CLS_ + c) * FRM + f];
    const float* tvd = d_tv + (size_t)(((s ^ 1) * FRM + rf) * CLS_ + rc) * DOUT;

    float sco = 0.f, sdi = 0.f;
#pragma unroll
    for (int jq = 0; jq < 4; jq++) {
        int o = lane + 32 * jq;
        float t0 = tap[o];
        float d0 = t0 - tvp[o]; sco = fmaf(d0, d0, sco);
        float d1 = t0 - tvd[o]; sdi = fmaf(d1, d1, sdi);
    }
#pragma unroll
    for (int off = 16; off; off >>= 1) {
        sco += __shfl_xor_sync(0xffffffffu, sco, off);
        sdi += __shfl_xor_sync(0xffffffffu, sdi, off);
    }
    if (!lane) {
        float pv = 1.f / (1.f + expf(-pred_v[(s * FRM + f) * CLS_ + c]));
        bool av = pv > 0.3f;
        float mco = (aa && av) ? 1.f : 0.f;
        float mdi = (aa && (f < num)) ? 1.f : 0.f;
        out[((0 * S_ + s) * CLS_ + c) * FRM + f] = sco * (1.f / 128.f) * mco;
        out[((1 * S_ + s) * CLS_ + c) * FRM + f] = sdi * (1.f / 128.f) * mdi;
    }
}

// =====================================================================
extern "C" void kernel_launch(void* const* d_in, const int* in_sizes, int n_in,
                              void* d_out, int out_size) {
    const float* feat_a = (const float*)d_in[0];
    const float* pred_a = (const float*)d_in[1];
    const float* feat_v = (const float*)d_in[2];
    const float* pred_v = (const float*)d_in[3];
    const float* cam    = (const float*)d_in[4];
    const int* rand_frames  = (const int*)d_in[5];
    const int* rand_classes = (const int*)d_in[6];
    const float* Wt = (const float*)d_in[7];
    const float* bt = (const float*)d_in[8];
    const float* Ws = (const float*)d_in[9];
    const float* bs = (const float*)d_in[10];
    const float* Wa = (const float*)d_in[11];
    const float* ba = (const float*)d_in[12];
    const float* Wv = (const float*)d_in[13];
    const float* bv = (const float*)d_in[14];
    float* out = (float*)d_out;

    static int inited = 0;
    static cudaStream_t s2 = 0;
    static cudaEvent_t eF = 0, eJ = 0;
    if (!inited) {
        inited = 1;
        cudaFuncSetAttribute(k_fa_mma, cudaFuncAttributeMaxDynamicSharedMemorySize, FA_SMEM);
        cudaFuncSetAttribute(k_g_mma, cudaFuncAttributeMaxDynamicSharedMemorySize, KG_SMEM);
        cudaFuncSetAttribute(k_tv_mma, cudaFuncAttributeMaxDynamicSharedMemorySize, TV_SMEM);
        if (cudaStreamCreateWithFlags(&s2, cudaStreamNonBlocking) != cudaSuccess) s2 = 0;
        if (s2) {
            if (cudaEventCreateWithFlags(&eF, cudaEventDisableTiming) != cudaSuccess) { eF = 0; }
            if (cudaEventCreateWithFlags(&eJ, cudaEventDisableTiming) != cudaSuccess) { eJ = 0; }
        }
    }
    const bool fork = (s2 != 0) && (eF != 0) && (eJ != 0);
    cudaStream_t vs = fork ? s2 : (cudaStream_t)0;

    if (fork) {
        cudaEventRecord(eF, 0);
        cudaStreamWaitEvent(s2, eF, 0);
    }

    // ---- audio chain (capture/default stream) ----
    k_cvt_w<<<64, 256>>>(Wt);                                 // 1
    // ---- video chain start (s2) ----
    k_prep_fvcam<<<(BV * D_ + BV * CLS_) / 16, 256, 0, vs>>>(feat_v, cam);  // 2
    // ---- audio main (ta fused into epilogue) ----
    k_fa_mma<<<BA, 128, FA_SMEM>>>(feat_a, bt, Wa, ba);       // 3

    // ---- video chain rest (s2) ----
    k_wbs<<<DOUT, 32, 0, vs>>>(Wv, bs);
    k_wvs<<<dim3(4, 8), 256, 0, vs>>>(Wv, Ws);
    k_g_mma<<<BV, 256, KG_SMEM, vs>>>();
    k_tv_mma<<<(BV * CLS_) / 128, 256, TV_SMEM, vs>>>(bv);

    if (fork) {
        cudaEventRecord(eJ, s2);
        cudaStreamWaitEvent(0, eJ, 0);
    }

    k_loss<<<dim3(S_, CLS_), 256>>>(pred_a, pred_v, rand_frames, rand_classes, out);
}

// round 16
// speedup vs baseline: 1.3131x; 1.3131x over previous
#include <cuda_runtime.h>
#include <cuda_fp16.h>
#include <math.h>
#include <cstdint>

// Problem constants
#define S_   32
#define FRM  8
#define CLS_ 32
#define D_   512
#define HWA2 64      // 8*8
#define HWV2 196     // 14*14
#define HWP  208     // padded to 13*16
#define DOUT 128
#define BA   (S_*CLS_)   // 1024
#define BV   (S_*FRM)    // 256

// ---------------- device scratch ----------------
__device__ float d_ta[BA * DOUT];
__device__ float d_camsum[BV * CLS_];
__device__ float d_tv[BV * CLS_ * DOUT];
__device__ float d_wbs[DOUT];
// fp16 permuted buffers
__device__ __half d_wt_h[D_ * D_];                      // [o][kperm]
__device__ __half d_wa_h[DOUT * D_];                    // [o][kperm]
__device__ __half d_fa_h[BA * D_];                      // [b][kperm(o)]
__device__ __half d_fv_h[(size_t)BV * D_ * HWP];        // [b][i][hwperm]
__device__ __half d_cam_h[(size_t)BV * CLS_ * HWP];     // [b][c][hwperm]
__device__ __half d_g_h[(size_t)BV * CLS_ * D_];        // [m][kperm]
__device__ __half d_wvs_h[DOUT * D_];                   // [o][kperm]

// =============== small asm helpers ===============
__device__ __forceinline__ uint32_t smem_to_u32(const void* p) {
    uint32_t a;
    asm("{ .reg .u64 t; cvta.to.shared.u64 t, %1; cvt.u32.u64 %0, t; }" : "=r"(a) : "l"(p));
    return a;
}
#define CP_ASYNC16(sm, g) \
    asm volatile("cp.async.cg.shared.global [%0], [%1], 16;" :: "r"((uint32_t)(sm)), "l"(g) : "memory")
#define CP_ASYNC_COMMIT() asm volatile("cp.async.commit_group;" ::: "memory")
#define CP_ASYNC_WAIT0()  asm volatile("cp.async.wait_group 0;" ::: "memory")
#define CP_ASYNC_WAIT1()  asm volatile("cp.async.wait_group 1;" ::: "memory")

#define LDS64(r0, r1, addr) \
    asm volatile("ld.shared.v2.b32 {%0,%1}, [%2];" : "=r"(r0), "=r"(r1) : "r"((uint32_t)(addr)))

#define MMA_F16(d, a, b) \
    asm volatile("mma.sync.aligned.m16n8k16.row.col.f32.f16.f16.f32 " \
        "{%0,%1,%2,%3}, {%4,%5,%6,%7}, {%8,%9}, {%0,%1,%2,%3};" \
        : "+f"((d)[0]), "+f"((d)[1]), "+f"((d)[2]), "+f"((d)[3]) \
        : "r"((a)[0]), "r"((a)[1]), "r"((a)[2]), "r"((a)[3]), "r"((b)[0]), "r"((b)[1]))

__device__ __forceinline__ uint32_t pack_h2(__half a, __half b) {
    __half2 p = __halves2half2(a, b);
    return *(uint32_t*)&p;
}

// k-permutation within a 16-group (m16n8k16 frag layout):
// word w (fp16 pair): w even -> k = w ; w odd -> k = w + 7.
// inverse (even k e): w = (e < 8) ? e : e - 7.

// =====================================================================
// Prep 1 (merged): Wt (blocks 0..63) and Wa (blocks 64..79) -> permuted fp16
// =====================================================================
__global__ __launch_bounds__(256) void k_cvt_w(const float* __restrict__ Wt,
                                               const float* __restrict__ Wa) {
    const int bx = blockIdx.x;
    const int which = (bx >= 64);
    const float* W = which ? Wa : Wt;
    int idx = (which ? (bx - 64) : bx) * 256 + threadIdx.x;
    int o = idx >> 5, g = idx & 31;
    const float* src = W + (size_t)o * D_ + g * 16;
    float v[16];
#pragma unroll
    for (int q = 0; q < 4; q++) {
        float4 f = *(const float4*)(src + q * 4);
        v[q * 4 + 0] = f.x; v[q * 4 + 1] = f.y; v[q * 4 + 2] = f.z; v[q * 4 + 3] = f.w;
    }
    uint32_t hw_[8];
#pragma unroll
    for (int w = 0; w < 8; w++) {
        int k = (w & 1) ? (w + 7) : w;
        hw_[w] = pack_h2(__float2half_rn(v[k]), __float2half_rn(v[k + 1]));
    }
    uint32_t* dh = (uint32_t*)(which ? d_wa_h : d_wt_h) + (size_t)o * 256 + g * 8;
    *(uint4*)(dh + 0) = make_uint4(hw_[0], hw_[1], hw_[2], hw_[3]);
    *(uint4*)(dh + 4) = make_uint4(hw_[4], hw_[5], hw_[6], hw_[7]);
}

// =====================================================================
// Prep (video): feat_v rows then cam rows -> fp16 hw-permuted (pad 208)
// =====================================================================
__global__ __launch_bounds__(256) void k_prep_fvcam(const float* __restrict__ feat_v,
                                                    const float* __restrict__ cam) {
    const int t = threadIdx.x;
    const int g = t & 15, rloc = t >> 4;
    const long row = (long)blockIdx.x * 16 + rloc;
    const bool is_cam = (row >= (long)BV * D_);
    long r2 = 0;
    const float* src;
    uint32_t* dst;
    if (!is_cam) {
        src = feat_v + row * HWV2;
        dst = (uint32_t*)d_fv_h + row * (HWP / 2) + g * 8;
    } else {
        r2 = row - (long)BV * D_;
        src = cam + r2 * HWV2;
        dst = (uint32_t*)d_cam_h + r2 * (HWP / 2) + g * 8;
    }
    const bool active = (g < 13);
    float v[16];
#pragma unroll
    for (int qq = 0; qq < 4; qq++) {
        int idx4 = g * 4 + qq;
        if (active && idx4 < 49) {
            float4 f = *(const float4*)(src + idx4 * 4);
            v[qq * 4 + 0] = f.x; v[qq * 4 + 1] = f.y;
            v[qq * 4 + 2] = f.z; v[qq * 4 + 3] = f.w;
        } else {
            v[qq * 4 + 0] = 0.f; v[qq * 4 + 1] = 0.f;
            v[qq * 4 + 2] = 0.f; v[qq * 4 + 3] = 0.f;
        }
    }
    if (active) {
        uint32_t wv[8];
#pragma unroll
        for (int w = 0; w < 8; w++) {
            int k = (w & 1) ? (w + 7) : w;
            wv[w] = pack_h2(__float2half_rn(v[k]), __float2half_rn(v[k + 1]));
        }
        *(uint4*)(dst + 0) = make_uint4(wv[0], wv[1], wv[2], wv[3]);
        *(uint4*)(dst + 4) = make_uint4(wv[4], wv[5], wv[6], wv[7]);
    }
    if (is_cam) {
        float s = 0.f;
#pragma unroll
        for (int q = 0; q < 16; q++) s += v[q];
        s += __shfl_xor_sync(0xffffffffu, s, 1);
        s += __shfl_xor_sync(0xffffffffu, s, 2);
        s += __shfl_xor_sync(0xffffffffu, s, 4);
        s += __shfl_xor_sync(0xffffffffu, s, 8);
        if (g == 0) d_camsum[r2] = s;
    }
}

// =====================================================================
// k_fa_mma: fa[b,o] = max_hw( feat[b,:,hw] . Wt[o,:] ) + bt[o]
// 128 threads (4 warps), 2 CTAs/SM. Warp tile 64o x 32hw.
// Epilogue writes fa as k-permuted fp16 (d_fa_h).
// =====================================================================
#define FEAT_OFF  1024
#define FEAT_ROWB 1056
#define FEAT_SZ   (64 * FEAT_ROWB)
#define WT_OFF    (FEAT_OFF + FEAT_SZ)
#define WT_ROWB   160
#define WT_BUFSZ  (128 * WT_ROWB)
#define FA_SMEM   (WT_OFF + 2 * WT_BUFSZ)   // 109568

__device__ __forceinline__ void fa_load_wt(uint32_t sb, int buf, int otp, int kc, int t) {
#pragma unroll
    for (int r = 0; r < 8; r++) {
        int idx = r * 128 + t;          // 1024 x 16B
        int row = idx >> 3, c = idx & 7;
        const __half* src = d_wt_h + ((size_t)(otp * 128 + row) * D_ + kc * 64 + c * 8);
        uint32_t dst = sb + WT_OFF + buf * WT_BUFSZ + row * WT_ROWB + c * 16;
        CP_ASYNC16(dst, src);
    }
}

__global__ void __launch_bounds__(128, 2) k_fa_mma(const float* __restrict__ feat_a,
                                                   const float* __restrict__ bt) {
    extern __shared__ char smem[];
    float* red = (float*)smem;          // 256 floats
    uint32_t sb = smem_to_u32(smem);
    const int b = blockIdx.x;
    const int t = threadIdx.x;
    const int w = t >> 5, lane = t & 31;
    const int oy = w >> 1, hx = w & 1;  // 2 o-groups(64) x 2 hw-groups(32)
    const int j = lane & 3, r4 = lane >> 2;

    // ---- pipelined prologue (two-sync): feat_a fp32 -> feat smem fp16 ----
    {
        const float* fsrc = feat_a + (size_t)b * (D_ * HWA2);
        const int hw = t & 63, kseg = t >> 6;   // kseg in {0,1}
#pragma unroll
        for (int r = 0; r < 8; r++) {
            int idx = r * 128 + t;              // 1024 x 16B
            int row = idx >> 4, c4 = idx & 15;
            CP_ASYNC16(sb + WT_OFF + row * 272 + c4 * 16,
                       fsrc + (size_t)row * HWA2 + c4 * 4);
        }
        CP_ASYNC_COMMIT();
        for (int c = 0; c < 8; c++) {
            if (c + 1 < 8) {
                uint32_t bb = sb + WT_OFF + ((c + 1) & 1) * WT_BUFSZ;
#pragma unroll
                for (int r = 0; r < 8; r++) {
                    int idx = r * 128 + t;
                    int row = idx >> 4, c4 = idx & 15;
                    CP_ASYNC16(bb + row * 272 + c4 * 16,
                               fsrc + (size_t)((c + 1) * 64 + row) * HWA2 + c4 * 4);
                }
                CP_ASYNC_COMMIT();
                CP_ASYNC_WAIT1();
            } else {
                CP_ASYNC_WAIT0();
            }
            __syncthreads();
            const float* stg = (const float*)(smem + WT_OFF + (c & 1) * WT_BUFSZ);
            const int hw = t & 63, kseg = t >> 6;
#pragma unroll
            for (int g2 = 0; g2 < 2; g2++) {
                const int kbase = kseg * 32 + g2 * 16;
                uint32_t pk[8];
#pragma unroll
                for (int ww = 0; ww < 8; ww++) {
                    int k = (ww & 1) ? (ww + 7) : ww;
                    pk[ww] = pack_h2(__float2half_rn(stg[(kbase + k) * 68 + hw]),
                                     __float2half_rn(stg[(kbase + k + 1) * 68 + hw]));
                }
                char* dst = smem + FEAT_OFF + hw * FEAT_ROWB
                          + (c * 128 + kseg * 64 + g2 * 32);
                *(uint4*)dst = make_uint4(pk[0], pk[1], pk[2], pk[3]);
                *(uint4*)(dst + 16) = make_uint4(pk[4], pk[5], pk[6], pk[7]);
            }
            __syncthreads();
        }
    }

    fa_load_wt(sb, 0, 0, 0, t);
    CP_ASYNC_COMMIT();

    float acc[4][4][4];
#pragma unroll
    for (int mf = 0; mf < 4; mf++)
#pragma unroll
        for (int nf = 0; nf < 4; nf++)
#pragma unroll
            for (int q = 0; q < 4; q++) acc[mf][nf][q] = 0.f;

    const int oA = oy * 64 + r4;       // + mf*16 (+8)
    const int hwB = hx * 32 + r4;      // + nf*8

    for (int it = 0; it < 32; it++) {
        const int otp = it >> 3, kc = it & 7, buf = it & 1;
        if (it + 1 < 32) {
            fa_load_wt(sb, buf ^ 1, (it + 1) >> 3, (it + 1) & 7, t);
            CP_ASYNC_COMMIT();
            CP_ASYNC_WAIT1();
        } else {
            CP_ASYNC_WAIT0();
        }
        __syncthreads();

        const uint32_t wtb = sb + WT_OFF + buf * WT_BUFSZ;
#pragma unroll
        for (int kst = 0; kst < 4; kst++) {
            const int ks = kc * 4 + kst;
            uint32_t a[4][4];
#pragma unroll
            for (int mf = 0; mf < 4; mf++) {
                uint32_t base = wtb + (oA + mf * 16) * WT_ROWB + kst * 32 + j * 8;
                LDS64(a[mf][0], a[mf][2], base);
                LDS64(a[mf][1], a[mf][3], base + 8 * WT_ROWB);
            }
            uint32_t bh[4][2];
#pragma unroll
            for (int nf = 0; nf < 4; nf++) {
                uint32_t bb = sb + FEAT_OFF + (hwB + nf * 8) * FEAT_ROWB + ks * 32 + j * 8;
                LDS64(bh[nf][0], bh[nf][1], bb);
            }
#pragma unroll
            for (int mf = 0; mf < 4; mf++)
#pragma unroll
                for (int nf = 0; nf < 4; nf++)
                    MMA_F16(acc[mf][nf], a[mf], bh[nf]);
        }

        if (kc == 7) {
#pragma unroll
            for (int mf = 0; mf < 4; mf++) {
                float m0 = -3.4e38f, m1 = -3.4e38f;
#pragma unroll
                for (int nf = 0; nf < 4; nf++) {
                    m0 = fmaxf(m0, fmaxf(acc[mf][nf][0], acc[mf][nf][1]));
                    m1 = fmaxf(m1, fmaxf(acc[mf][nf][2], acc[mf][nf][3]));
                }
                m0 = fmaxf(m0, __shfl_xor_sync(0xffffffffu, m0, 1));
                m0 = fmaxf(m0, __shfl_xor_sync(0xffffffffu, m0, 2));
                m1 = fmaxf(m1, __shfl_xor_sync(0xffffffffu, m1, 1));
                m1 = fmaxf(m1, __shfl_xor_sync(0xffffffffu, m1, 2));
                if (j == 0) {
                    int o0 = oy * 64 + mf * 16 + r4;
                    red[o0 * 2 + hx] = m0;
                    red[(o0 + 8) * 2 + hx] = m1;
                }
            }
            __syncthreads();
            {
                int o = t;   // 128 threads, 128 o-rows
                float v = fmaxf(red[o * 2], red[o * 2 + 1]);
                int og = otp * 128 + o;
                v += bt[og];
                int gg = og >> 4, ke = og & 15;
                int kel = ke & ~1;
                int wd = (kel < 8) ? kel : (kel - 7);
                d_fa_h[(size_t)b * D_ + gg * 16 + wd * 2 + (ke & 1)] = __float2half_rn(v);
            }
#pragma unroll
            for (int mf = 0; mf < 4; mf++)
#pragma unroll
                for (int nf = 0; nf < 4; nf++)
#pragma unroll
                    for (int q = 0; q < 4; q++) acc[mf][nf][q] = 0.f;
        }
        __syncthreads();
    }
}

// =====================================================================
// k_g_mma: g[b,c,i] = sum_hw cam*feat_v -> fp16 k-permuted d_g_h
// =====================================================================
#define GC_OFF   1024
#define G_ROWB   416
#define GC_SZ    (32 * G_ROWB)
#define GF_OFF   (GC_OFF + GC_SZ)
#define GF_BUFSZ (128 * G_ROWB)
#define KG_SMEM  (GF_OFF + 2 * GF_BUFSZ)

__device__ __forceinline__ void g_load_fv(uint32_t sb, int buf, int b, int ic, int t) {
#pragma unroll
    for (int r = 0; r < 13; r++) {
        int idx = r * 256 + t;
        int row = idx / 26, c = idx % 26;
        const __half* src = d_fv_h + ((size_t)(b * D_) + ic * 128 + row) * HWP + c * 8;
        uint32_t dst = sb + GF_OFF + buf * GF_BUFSZ + row * G_ROWB + c * 16;
        CP_ASYNC16(dst, src);
    }
}

__global__ void __launch_bounds__(256, 1) k_g_mma() {
    extern __shared__ char smem[];
    uint32_t sb = smem_to_u32(smem);
    const int b = blockIdx.x;
    const int t = threadIdx.x;
    const int w = t >> 5, lane = t & 31;
    const int my = w & 1, ix = w >> 1;
    const int j = lane & 3, r4 = lane >> 2;

#pragma unroll
    for (int r = 0; r < 4; r++) {
        int idx = r * 256 + t;
        if (idx < 832) {
            int row = idx / 26, c = idx % 26;
            const __half* src = d_cam_h + ((size_t)(b * CLS_) + row) * HWP + c * 8;
            CP_ASYNC16(sb + GC_OFF + row * G_ROWB + c * 16, src);
        }
    }
    g_load_fv(sb, 0, b, 0, t);
    CP_ASYNC_COMMIT();

    for (int ic = 0; ic < 4; ic++) {
        const int buf = ic & 1;
        if (ic + 1 < 4) {
            g_load_fv(sb, buf ^ 1, b, ic + 1, t);
            CP_ASYNC_COMMIT();
            CP_ASYNC_WAIT1();
        } else {
            CP_ASYNC_WAIT0();
        }
        __syncthreads();

        float acc[4][4];
#pragma unroll
        for (int nf = 0; nf < 4; nf++)
#pragma unroll
            for (int q = 0; q < 4; q++) acc[nf][q] = 0.f;

        const uint32_t fvb = sb + GF_OFF + buf * GF_BUFSZ;
#pragma unroll
        for (int kst = 0; kst < 13; kst++) {
            uint32_t a[4];
            uint32_t abase = sb + GC_OFF + (my * 16 + r4) * G_ROWB + kst * 32 + j * 8;
            LDS64(a[0], a[2], abase);
            LDS64(a[1], a[3], abase + 8 * G_ROWB);
            uint32_t bh[4][2];
#pragma unroll
            for (int nf = 0; nf < 4; nf++) {
                uint32_t bb = fvb + (ix * 32 + nf * 8 + r4) * G_ROWB + kst * 32 + j * 8;
                LDS64(bh[nf][0], bh[nf][1], bb);
            }
#pragma unroll
            for (int nf = 0; nf < 4; nf++)
                MMA_F16(acc[nf], a, bh[nf]);
        }

        const int c0 = my * 16 + r4;
#pragma unroll
        for (int nf = 0; nf < 4; nf++) {
            int ig = ic * 128 + ix * 32 + nf * 8 + 2 * j;
            int gg = ig >> 4, rm = ig & 15;
            int wd = (rm < 8) ? rm : (rm - 7);
            int word = gg * 8 + wd;
            uint32_t* g0 = (uint32_t*)d_g_h + ((size_t)b * CLS_ + c0) * 256 + word;
            *g0 = pack_h2(__float2half_rn(acc[nf][0]), __float2half_rn(acc[nf][1]));
            uint32_t* g1 = (uint32_t*)d_g_h + ((size_t)b * CLS_ + c0 + 8) * 256 + word;
            *g1 = pack_h2(__float2half_rn(acc[nf][2]), __float2half_rn(acc[nf][3]));
        }
        __syncthreads();
    }
}

// =====================================================================
// wbs[o] = Wv[o,:].bs   — grid 16 x 256 threads, warp-per-o
// =====================================================================
__global__ __launch_bounds__(256) void k_wbs(const float* __restrict__ Wv,
                                             const float* __restrict__ bs) {
    int o = blockIdx.x * 8 + (threadIdx.x >> 5);
    int lane = threadIdx.x & 31;
    float s = 0.f;
#pragma unroll 4
    for (int d = lane; d < D_; d += 32) s = fmaf(Wv[(size_t)o * D_ + d], bs[d], s);
#pragma unroll
    for (int off = 16; off; off >>= 1) s += __shfl_xor_sync(0xffffffffu, s, off);
    if (!lane) d_wbs[o] = s;
}

// =====================================================================
// Wvs[o,i] = sum_d Wv[o,d]*Ws[d,i]  (fp16 permuted out)
// =====================================================================
__global__ __launch_bounds__(256) void k_wvs(const float* __restrict__ Wv,
                                             const float* __restrict__ Ws) {
    __shared__ float sV[32][65];
    __shared__ float sS[64][65];
    const int oT = blockIdx.x, iT = blockIdx.y;
    const int t = threadIdx.x;
    const int tx = t & 31, ty = t >> 5;

    float acc[4][2];
#pragma unroll
    for (int a = 0; a < 4; a++) { acc[a][0] = 0.f; acc[a][1] = 0.f; }

    for (int k0 = 0; k0 < D_; k0 += 64) {
#pragma unroll
        for (int r = 0; r < 8; r++) {
            int idx = r * 256 + t;
            int o = idx >> 6, kk = idx & 63;
            sV[o][kk] = Wv[(size_t)(oT * 32 + o) * D_ + k0 + kk];
        }
#pragma unroll
        for (int r = 0; r < 16; r++) {
            int idx = r * 256 + t;
            int kk = idx >> 6, i = idx & 63;
            sS[kk][i] = Ws[(size_t)(k0 + kk) * D_ + iT * 64 + i];
        }
        __syncthreads();
#pragma unroll
        for (int kk = 0; kk < 64; kk++) {
            float bb0 = sS[kk][tx], bb1 = sS[kk][tx + 32];
#pragma unroll
            for (int a = 0; a < 4; a++) {
                float av = sV[ty * 4 + a][kk];
                acc[a][0] = fmaf(av, bb0, acc[a][0]);
                acc[a][1] = fmaf(av, bb1, acc[a][1]);
            }
        }
        __syncthreads();
    }
#pragma unroll
    for (int a = 0; a < 4; a++) {
        int o = oT * 32 + ty * 4 + a;
#pragma unroll
        for (int half_ = 0; half_ < 2; half_++) {
            int i = iT * 64 + tx + 32 * half_;
            float v = acc[a][half_];
            int gg = i >> 4;
            int ke = (i & ~1) & 15;
            int wd = (ke < 8) ? ke : (ke - 7);
            d_wvs_h[(size_t)o * D_ + gg * 16 + wd * 2 + (i & 1)] = __float2half_rn(v);
        }
    }
}

// =====================================================================
// k_tv_mma: 128m x 128o tiles (grid 64)
// =====================================================================
#define TV_B_OFF   0
#define TV_B_ROWB  1056
#define TV_A_OFF   (128 * TV_B_ROWB)
#define TV_A_ROWB  288
#define TV_A_BUFSZ (128 * TV_A_ROWB)
#define TV_SMEM    (TV_A_OFF + 2 * TV_A_BUFSZ)

__device__ __forceinline__ void tv_load_a(uint32_t sb, int buf, const __half* A,
                                          int m0, int kc, int t) {
#pragma unroll
    for (int r = 0; r < 8; r++) {
        int idx = r * 256 + t;
        int row = idx >> 4, c = idx & 15;
        const __half* src = A + ((size_t)(m0 + row) * D_ + kc * 128 + c * 8);
        uint32_t dst = sb + TV_A_OFF + buf * TV_A_BUFSZ + row * TV_A_ROWB + c * 16;
        CP_ASYNC16(dst, src);
    }
}

__global__ void __launch_bounds__(256, 1) k_tv_mma(const float* __restrict__ bv) {
    extern __shared__ char smem[];
    uint32_t sb = smem_to_u32(smem);
    const int m0 = blockIdx.x * 128;
    const int t = threadIdx.x;
    const int w = t >> 5, lane = t & 31;
    const int mgrp = w & 3, ogrp = w >> 2;
    const int j = lane & 3, r4 = lane >> 2;

    float acc[2][8][4];
#pragma unroll
    for (int mf = 0; mf < 2; mf++)
#pragma unroll
        for (int nf = 0; nf < 8; nf++)
#pragma unroll
            for (int q = 0; q < 4; q++) acc[mf][nf][q] = 0.f;

#pragma unroll
    for (int r = 0; r < 32; r++) {
        int idx = r * 256 + t;
        int row = idx >> 6, c = idx & 63;
        CP_ASYNC16(sb + TV_B_OFF + row * TV_B_ROWB + c * 16,
                   d_wvs_h + ((size_t)row * D_ + c * 8));
    }
    tv_load_a(sb, 0, d_g_h, m0, 0, t);
    CP_ASYNC_COMMIT();

    for (int kc = 0; kc < 4; kc++) {
        const int buf = kc & 1;
        if (kc + 1 < 4) {
            tv_load_a(sb, buf ^ 1, d_g_h, m0, kc + 1, t);
            CP_ASYNC_COMMIT();
            CP_ASYNC_WAIT1();
        } else {
            CP_ASYNC_WAIT0();
        }
        __syncthreads();

#pragma unroll
        for (int kst = 0; kst < 8; kst++) {
            const int ks = kc * 8 + kst;
            uint32_t a[2][4];
#pragma unroll
            for (int mf = 0; mf < 2; mf++) {
                uint32_t base = sb + TV_A_OFF + buf * TV_A_BUFSZ
                              + (mgrp * 32 + mf * 16 + r4) * TV_A_ROWB + kst * 32 + j * 8;
                LDS64(a[mf][0], a[mf][2], base);
                LDS64(a[mf][1], a[mf][3], base + 8 * TV_A_ROWB);
            }
            uint32_t bh[8][2];
#pragma unroll
            for (int nf = 0; nf < 8; nf++) {
                uint32_t bb = sb + TV_B_OFF + (ogrp * 64 + nf * 8 + r4) * TV_B_ROWB
                            + ks * 32 + j * 8;
                LDS64(bh[nf][0], bh[nf][1], bb);
            }
#pragma unroll
            for (int mf = 0; mf < 2; mf++)
#pragma unroll
                for (int nf = 0; nf < 8; nf++)
                    MMA_F16(acc[mf][nf], a[mf], bh[nf]);
        }
        __syncthreads();
    }

#pragma unroll
    for (int mf = 0; mf < 2; mf++) {
        int mr0 = m0 + mgrp * 32 + mf * 16 + r4;
        int mr1 = mr0 + 8;
        float cs0 = d_camsum[mr0], cs1 = d_camsum[mr1];
        float inv0 = 1.f / (cs0 + 1e-10f), inv1 = 1.f / (cs1 + 1e-10f);
#pragma unroll
        for (int nf = 0; nf < 8; nf++) {
            int o0 = ogrp * 64 + nf * 8 + 2 * j;
            float wb0 = d_wbs[o0], wb1 = d_wbs[o0 + 1];
            float bv0 = bv[o0], bv1 = bv[o0 + 1];
            d_tv[(size_t)mr0 * DOUT + o0]     = (acc[mf][nf][0] + wb0 * cs0) * inv0 + bv0;
            d_tv[(size_t)mr0 * DOUT + o0 + 1] = (acc[mf][nf][1] + wb1 * cs0) * inv0 + bv1;
            d_tv[(size_t)mr1 * DOUT + o0]     = (acc[mf][nf][2] + wb0 * cs1) * inv1 + bv0;
            d_tv[(size_t)mr1 * DOUT + o0 + 1] = (acc[mf][nf][3] + wb1 * cs1) * inv1 + bv1;
        }
    }
}

// =====================================================================
// k_ta_mma: 64m x 128o tiles (grid 16) — 2 m-warps x 4 o-warps
// =====================================================================
#define TA_A_ROWB  288
#define TA_A_BUFSZ (64 * TA_A_ROWB)       // 18432
#define TA_SMEM    (TV_A_OFF + 2 * TA_A_BUFSZ)   // 172032

__device__ __forceinline__ void ta_load_a(uint32_t sb, int buf, int m0, int kc, int t) {
#pragma unroll
    for (int r = 0; r < 4; r++) {
        int idx = r * 256 + t;
        int row = idx >> 4, c = idx & 15;
        const __half* src = d_fa_h + ((size_t)(m0 + row) * D_ + kc * 128 + c * 8);
        uint32_t dst = sb + TV_A_OFF + buf * TA_A_BUFSZ + row * TA_A_ROWB + c * 16;
        CP_ASYNC16(dst, src);
    }
}

__global__ void __launch_bounds__(256, 1) k_ta_mma(const float* __restrict__ ba) {
    extern __shared__ char smem[];
    uint32_t sb = smem_to_u32(smem);
    const int m0 = blockIdx.x * 64;
    const int t = threadIdx.x;
    const int w = t >> 5, lane = t & 31;
    const int mgrp = w & 1, ogrp = w >> 1;     // 2 m-warps x 4 o-warps
    const int j = lane & 3, r4 = lane >> 2;

    float acc[2][4][4];
#pragma unroll
    for (int mf = 0; mf < 2; mf++)
#pragma unroll
        for (int nf = 0; nf < 4; nf++)
#pragma unroll
            for (int q = 0; q < 4; q++) acc[mf][nf][q] = 0.f;

#pragma unroll
    for (int r = 0; r < 32; r++) {
        int idx = r * 256 + t;
        int row = idx >> 6, c = idx & 63;
        CP_ASYNC16(sb + TV_B_OFF + row * TV_B_ROWB + c * 16,
                   d_wa_h + ((size_t)row * D_ + c * 8));
    }
    ta_load_a(sb, 0, m0, 0, t);
    CP_ASYNC_COMMIT();

    for (int kc = 0; kc < 4; kc++) {
        const int buf = kc & 1;
        if (kc + 1 < 4) {
            ta_load_a(sb, buf ^ 1, m0, kc + 1, t);
            CP_ASYNC_COMMIT();
            CP_ASYNC_WAIT1();
        } else {
            CP_ASYNC_WAIT0();
        }
        __syncthreads();

#pragma unroll
        for (int kst = 0; kst < 8; kst++) {
            const int ks = kc * 8 + kst;
            uint32_t a[2][4];
#pragma unroll
            for (int mf = 0; mf < 2; mf++) {
                uint32_t base = sb + TV_A_OFF + buf * TA_A_BUFSZ
                              + (mgrp * 32 + mf * 16 + r4) * TA_A_ROWB + kst * 32 + j * 8;
                LDS64(a[mf][0], a[mf][2], base);
                LDS64(a[mf][1], a[mf][3], base + 8 * TA_A_ROWB);
            }
            uint32_t bh[4][2];
#pragma unroll
            for (int nf = 0; nf < 4; nf++) {
                uint32_t bb = sb + TV_B_OFF + (ogrp * 32 + nf * 8 + r4) * TV_B_ROWB
                            + ks * 32 + j * 8;
                LDS64(bh[nf][0], bh[nf][1], bb);
            }
#pragma unroll
            for (int mf = 0; mf < 2; mf++)
#pragma unroll
                for (int nf = 0; nf < 4; nf++)
                    MMA_F16(acc[mf][nf], a[mf], bh[nf]);
        }
        __syncthreads();
    }

#pragma unroll
    for (int mf = 0; mf < 2; mf++) {
        int mr0 = m0 + mgrp * 32 + mf * 16 + r4;
        int mr1 = mr0 + 8;
#pragma unroll
        for (int nf = 0; nf < 4; nf++) {
            int o0 = ogrp * 32 + nf * 8 + 2 * j;
            float ba0 = ba[o0], ba1 = ba[o0 + 1];
            d_ta[(size_t)mr0 * DOUT + o0]     = acc[mf][nf][0] + ba0;
            d_ta[(size_t)mr0 * DOUT + o0 + 1] = acc[mf][nf][1] + ba1;
            d_ta[(size_t)mr1 * DOUT + o0]     = acc[mf][nf][2] + ba0;
            d_ta[(size_t)mr1 * DOUT + o0 + 1] = acc[mf][nf][3] + ba1;
        }
    }
}

// =====================================================================
// losses
// =====================================================================
__global__ void k_loss(const float* __restrict__ pred_a, const float* __restrict__ pred_v,
                       const int* __restrict__ rand_frames, const int* __restrict__ rand_classes,
                       float* __restrict__ out) {
    const int s = blockIdx.x, c = blockIdx.y;
    const int f = threadIdx.x >> 5, lane = threadIdx.x & 31;

    const float pa = pred_a[s * CLS_ + c];
    const bool aa = pa > 0.3f;
    const int num = (int)(pa * (float)FRM);

    const float* tap = d_ta + (size_t)(s * CLS_ + c) * DOUT;
    const float* tvp = d_tv + (size_t)((s * FRM + f) * CLS_ + c) * DOUT;
    const int rf = rand_frames[(s * CLS_ + c) * FRM + f];
    const int rc = rand_classes[(s * CLS_ + c) * FRM + f];
    const float* tvd = d_tv + (size_t)(((s ^ 1) * FRM + rf) * CLS_ + rc) * DOUT;

    float sco = 0.f, sdi = 0.f;
#pragma unroll
    for (int jq = 0; jq < 4; jq++) {
        int o = lane + 32 * jq;
        float t0 = tap[o];
        float d0 = t0 - tvp[o]; sco = fmaf(d0, d0, sco);
        float d1 = t0 - tvd[o]; sdi = fmaf(d1, d1, sdi);
    }
#pragma unroll
    for (int off = 16; off; off >>= 1) {
        sco += __shfl_xor_sync(0xffffffffu, sco, off);
        sdi += __shfl_xor_sync(0xffffffffu, sdi, off);
    }
    if (!lane) {
        float pv = 1.f / (1.f + expf(-pred_v[(s * FRM + f) * CLS_ + c]));
        bool av = pv > 0.3f;
        float mco = (aa && av) ? 1.f : 0.f;
        float mdi = (aa && (f < num)) ? 1.f : 0.f;
        out[((0 * S_ + s) * CLS_ + c) * FRM + f] = sco * (1.f / 128.f) * mco;
        out[((1 * S_ + s) * CLS_ + c) * FRM + f] = sdi * (1.f / 128.f) * mdi;
    }
}

// =====================================================================
extern "C" void kernel_launch(void* const* d_in, const int* in_sizes, int n_in,
                              void* d_out, int out_size) {
    const float* feat_a = (const float*)d_in[0];
    const float* pred_a = (const float*)d_in[1];
    const float* feat_v = (const float*)d_in[2];
    const float* pred_v = (const float*)d_in[3];
    const float* cam    = (const float*)d_in[4];
    const int* rand_frames  = (const int*)d_in[5];
    const int* rand_classes = (const int*)d_in[6];
    const float* Wt = (const float*)d_in[7];
    const float* bt = (const float*)d_in[8];
    const float* Ws = (const float*)d_in[9];
    const float* bs = (const float*)d_in[10];
    const float* Wa = (const float*)d_in[11];
    const float* ba = (const float*)d_in[12];
    const float* Wv = (const float*)d_in[13];
    const float* bv = (const float*)d_in[14];
    float* out = (float*)d_out;

    static int inited = 0;
    static cudaStream_t s2 = 0;
    static cudaEvent_t eF = 0, eJ = 0;
    if (!inited) {
        inited = 1;
        cudaFuncSetAttribute(k_fa_mma, cudaFuncAttributeMaxDynamicSharedMemorySize, FA_SMEM);
        cudaFuncSetAttribute(k_g_mma, cudaFuncAttributeMaxDynamicSharedMemorySize, KG_SMEM);
        cudaFuncSetAttribute(k_tv_mma, cudaFuncAttributeMaxDynamicSharedMemorySize, TV_SMEM);
        cudaFuncSetAttribute(k_ta_mma, cudaFuncAttributeMaxDynamicSharedMemorySize, TA_SMEM);
        if (cudaStreamCreateWithFlags(&s2, cudaStreamNonBlocking) != cudaSuccess) s2 = 0;
        if (s2) {
            if (cudaEventCreateWithFlags(&eF, cudaEventDisableTiming) != cudaSuccess) { eF = 0; }
            if (cudaEventCreateWithFlags(&eJ, cudaEventDisableTiming) != cudaSuccess) { eJ = 0; }
        }
    }
    const bool fork = (s2 != 0) && (eF != 0) && (eJ != 0);
    cudaStream_t vs = fork ? s2 : (cudaStream_t)0;

    if (fork) {
        cudaEventRecord(eF, 0);
        cudaStreamWaitEvent(s2, eF, 0);
    }

    // ---- audio chain (capture/default stream) ----
    k_cvt_w<<<80, 256>>>(Wt, Wa);                             // 1
    // ---- video chain start (s2) ----
    k_prep_fvcam<<<(BV * D_ + BV * CLS_) / 16, 256, 0, vs>>>(feat_v, cam);  // 2
    // ---- audio main ----
    k_fa_mma<<<BA, 128, FA_SMEM>>>(feat_a, bt);               // 3
    k_ta_mma<<<BA / 64, 256, TA_SMEM>>>(ba);                  // 4

    // ---- video chain rest (s2) ----
    k_wbs<<<16, 256, 0, vs>>>(Wv, bs);
    k_wvs<<<dim3(4, 8), 256, 0, vs>>>(Wv, Ws);
    k_g_mma<<<BV, 256, KG_SMEM, vs>>>();
    k_tv_mma<<<(BV * CLS_) / 128, 256, TV_SMEM, vs>>>(bv);

    if (fork) {
        cudaEventRecord(eJ, s2);
        cudaStreamWaitEvent(0, eJ, 0);
    }

    k_loss<<<dim3(S_, CLS_), 256>>>(pred_a, pred_v, rand_frames, rand_classes, out);
}